// round 14
// baseline (speedup 1.0000x reference)
#include <cuda_runtime.h>
#include <cstdint>
#include <cstddef>

// Problem constants
#define T_TOKENS 65536
#define DM 2048
#define NE 64

// Tiling: 1-warp CTAs, 64 tokens/CTA, per-thread 16 tokens x 8 experts.
// KC=32 chunks, cp.async double-buffered global->smem pipeline (no prefetch
// registers -> no spills, unlike R7's 255-reg version).
#define KC 32
#define NCHUNK (DM / KC)     // 64
#define TCTA 64

// Output layout (flattened tuple, all float32) — validated R4+:
#define TP_OFF ((size_t)T_TOKENS * NE)
#define LG_OFF ((size_t)T_TOKENS * NE + T_TOKENS)

typedef unsigned long long ull;

__device__ __forceinline__ ull fma2(ull a, ull b, ull c) {
    ull d;
    asm("fma.rn.f32x2 %0, %1, %2, %3;" : "=l"(d) : "l"(a), "l"(b), "l"(c));
    return d;
}
__device__ __forceinline__ ull dup2(float w) {
    ull d;
    asm("mov.b64 %0, {%1, %1};" : "=l"(d) : "f"(w));
    return d;
}
__device__ __forceinline__ ull pack2(float lo, float hi) {
    ull d;
    asm("mov.b64 %0, {%1, %2};" : "=l"(d) : "f"(lo), "f"(hi));
    return d;
}
__device__ __forceinline__ float2 unpack2(ull u) {
    float2 f;
    asm("mov.b64 {%0, %1}, %2;" : "=f"(f.x), "=f"(f.y) : "l"(u));
    return f;
}
__device__ __forceinline__ void cp16(uint32_t dst, const void* src) {
    asm volatile("cp.async.cg.shared.global [%0], [%1], 16;"
                 :: "r"(dst), "l"(src));
}

__global__ void __launch_bounds__(32)
router_kernel(const float* __restrict__ x,
              const float* __restrict__ W,
              float* __restrict__ out) {
    // Rows are exactly 32 floats (128B). 16B-granule XOR swizzle gives
    // conflict-free compute loads AND direct cp.async fills:
    //   x granule (t,g)  stored at col 4*(g ^ ((t>>4)&3))
    //   W granule (e,g)  stored at col 4*(g ^ (e&7))
    __shared__ __align__(16) float xsm[2][TCTA * KC];   // 2 x 8 KB
    __shared__ __align__(16) float wsm[2][NE * KC];     // 2 x 8 KB

    const int lane = threadIdx.x;
    const int tx   = lane & 7;        // expert lane: e = tx + 8j
    const int tyq  = lane >> 3;       // token group: tokens tyq*16 .. +15
    const int t0   = blockIdx.x * TCTA;
    const int tbase = tyq * 16;

    // fill mapping: 4 rows x 8 granules per pass, 16 passes
    const int fr = lane >> 3;         // row sub-index 0..3
    const int fg = lane & 7;          // 16B granule 0..7

    const uint32_t xs_a = (uint32_t)__cvta_generic_to_shared(&xsm[0][0]);
    const uint32_t ws_a = (uint32_t)__cvta_generic_to_shared(&wsm[0][0]);

    // acc[p][j]: token pair (tbase+2p, tbase+2p+1) x expert (tx+8j)
    ull acc[8][8];
#pragma unroll
    for (int p = 0; p < 8; p++)
#pragma unroll
        for (int j = 0; j < 8; j++) acc[p][j] = 0ull;

    // ---- async fill of chunk (k0) into buffer buf ----
    auto fill = [&](int buf, int k0) {
        const uint32_t xb = xs_a + (uint32_t)buf * (TCTA * KC * 4);
        const uint32_t wb = ws_a + (uint32_t)buf * (NE * KC * 4);
#pragma unroll
        for (int rr = 0; rr < 16; rr++) {
            const int r = fr + 4 * rr;                 // token-local / expert
            const uint32_t dx = xb + (uint32_t)(r * KC + ((fg ^ ((r >> 4) & 3)) << 2)) * 4;
            cp16(dx, x + (size_t)(t0 + r) * DM + k0 + fg * 4);
            const uint32_t dw = wb + (uint32_t)(r * KC + ((fg ^ (r & 7)) << 2)) * 4;
            cp16(dw, W + (size_t)r * DM + k0 + fg * 4);
        }
        asm volatile("cp.async.commit_group;");
    };

    // prologue: start chunk 0
    fill(0, 0);

    const int xswz = tyq << 2;
    const int wswz = tx << 2;

    for (int c = 0; c < NCHUNK; c++) {
        const int buf = c & 1;

        if (c + 1 < NCHUNK) {
            fill(buf ^ 1, (c + 1) * KC);               // overlap with compute
            asm volatile("cp.async.wait_group 1;");    // chunk c landed
        } else {
            asm volatile("cp.async.wait_group 0;");
        }
        __syncwarp();

        const float* xb = &xsm[buf][tbase * KC];
        const float* wb = &wsm[buf][0];

        // per k: 16 scalar LDS (x) + 8 scalar LDS (w) = 24 wf,
        //        64 FFMA2 = 128 SMSP-cycles -> 4L/F = 0.75
#pragma unroll 8
        for (int kk = 0; kk < KC; kk++) {
            const int kx = kk ^ xswz;
            const int kw = kk ^ wswz;
            ull wd[8];
#pragma unroll
            for (int j = 0; j < 8; j++)
                wd[j] = dup2(wb[(tx + 8 * j) * KC + kw]);
            ull xp[8];
#pragma unroll
            for (int p = 0; p < 8; p++)
                xp[p] = pack2(xb[(2 * p) * KC + kx],
                              xb[(2 * p + 1) * KC + kx]);
#pragma unroll
            for (int p = 0; p < 8; p++)
#pragma unroll
                for (int j = 0; j < 8; j++)
                    acc[p][j] = fma2(xp[p], wd[j], acc[p][j]);
        }
    }

    // ---- epilogue: softmax/argmax per token over the 8 tx-lanes ----
#pragma unroll
    for (int p = 0; p < 8; p++) {
        float la[2][8];
#pragma unroll
        for (int j = 0; j < 8; j++) {
            float2 f = unpack2(acc[p][j]);
            la[0][j] = f.x;
            la[1][j] = f.y;
        }
#pragma unroll
        for (int a = 0; a < 2; a++) {
            const int t = t0 + tbase + 2 * p + a;

            // local argmax; expert ids tx+8j strictly increase with j ->
            // strict '>' keeps the FIRST max (matches jnp.argmax)
            float m = la[a][0];
            int   e = tx;
#pragma unroll
            for (int j = 1; j < 8; j++) {
                const int ej = tx + 8 * j;
                if (la[a][j] > m) { m = la[a][j]; e = ej; }
            }
            // butterfly over the 8-lane tx group (lane = tx + 8*tyq)
#pragma unroll
            for (int msk = 1; msk < 8; msk <<= 1) {
                float om = __shfl_xor_sync(0xffffffffu, m, msk);
                int   oe = __shfl_xor_sync(0xffffffffu, e, msk);
                if (om > m || (om == m && oe < e)) { m = om; e = oe; }
            }

            float s = 0.f;
#pragma unroll
            for (int j = 0; j < 8; j++) s += __expf(la[a][j] - m);
#pragma unroll
            for (int msk = 1; msk < 8; msk <<= 1)
                s += __shfl_xor_sync(0xffffffffu, s, msk);

            float* lg = out + LG_OFF + (size_t)t * NE;
            float* oh = out + (size_t)t * NE;
#pragma unroll
            for (int j = 0; j < 8; j++) {
                const int ej = tx + 8 * j;
                lg[ej] = la[a][j];
                oh[ej] = (ej == e) ? 1.f : 0.f;
            }
            if (tx == 0) out[TP_OFF + t] = 1.0f / s;
        }
    }
}

extern "C" void kernel_launch(void* const* d_in, const int* in_sizes, int n_in,
                              void* d_out, int out_size) {
    const float* x = (const float*)d_in[0];   // [65536, 2048] f32
    const float* W = (const float*)d_in[1];   // [64, 2048] f32
    float* out = (float*)d_out;

    dim3 grid(T_TOKENS / TCTA);   // 1024 one-warp CTAs
    dim3 block(32);
    router_kernel<<<grid, block>>>(x, W, out);
}

// round 15
// speedup vs baseline: 1.0001x; 1.0001x over previous
#include <cuda_runtime.h>
#include <cstdint>
#include <cstddef>

// Problem constants
#define T_TOKENS 65536
#define DM 2048
#define NE 64

// Tiling: 1-warp CTAs, 64 tokens/CTA, per-thread 16 tokens x 8 experts.
// KC=32 chunks, cp.async double-buffered global->smem pipeline (no prefetch
// registers -> no spills, unlike R7's 255-reg version).
#define KC 32
#define NCHUNK (DM / KC)     // 64
#define TCTA 64

// Output layout (flattened tuple, all float32) — validated R4+:
#define TP_OFF ((size_t)T_TOKENS * NE)
#define LG_OFF ((size_t)T_TOKENS * NE + T_TOKENS)

typedef unsigned long long ull;

__device__ __forceinline__ ull fma2(ull a, ull b, ull c) {
    ull d;
    asm("fma.rn.f32x2 %0, %1, %2, %3;" : "=l"(d) : "l"(a), "l"(b), "l"(c));
    return d;
}
__device__ __forceinline__ ull dup2(float w) {
    ull d;
    asm("mov.b64 %0, {%1, %1};" : "=l"(d) : "f"(w));
    return d;
}
__device__ __forceinline__ ull pack2(float lo, float hi) {
    ull d;
    asm("mov.b64 %0, {%1, %2};" : "=l"(d) : "f"(lo), "f"(hi));
    return d;
}
__device__ __forceinline__ float2 unpack2(ull u) {
    float2 f;
    asm("mov.b64 {%0, %1}, %2;" : "=f"(f.x), "=f"(f.y) : "l"(u));
    return f;
}
__device__ __forceinline__ void cp16(uint32_t dst, const void* src) {
    asm volatile("cp.async.cg.shared.global [%0], [%1], 16;"
                 :: "r"(dst), "l"(src));
}

__global__ void __launch_bounds__(32)
router_kernel(const float* __restrict__ x,
              const float* __restrict__ W,
              float* __restrict__ out) {
    // Rows are exactly 32 floats (128B). 16B-granule XOR swizzle gives
    // conflict-free compute loads AND direct cp.async fills:
    //   x granule (t,g)  stored at col 4*(g ^ ((t>>4)&3))
    //   W granule (e,g)  stored at col 4*(g ^ (e&7))
    __shared__ __align__(16) float xsm[2][TCTA * KC];   // 2 x 8 KB
    __shared__ __align__(16) float wsm[2][NE * KC];     // 2 x 8 KB

    const int lane = threadIdx.x;
    const int tx   = lane & 7;        // expert lane: e = tx + 8j
    const int tyq  = lane >> 3;       // token group: tokens tyq*16 .. +15
    const int t0   = blockIdx.x * TCTA;
    const int tbase = tyq * 16;

    // fill mapping: 4 rows x 8 granules per pass, 16 passes
    const int fr = lane >> 3;         // row sub-index 0..3
    const int fg = lane & 7;          // 16B granule 0..7

    const uint32_t xs_a = (uint32_t)__cvta_generic_to_shared(&xsm[0][0]);
    const uint32_t ws_a = (uint32_t)__cvta_generic_to_shared(&wsm[0][0]);

    // acc[p][j]: token pair (tbase+2p, tbase+2p+1) x expert (tx+8j)
    ull acc[8][8];
#pragma unroll
    for (int p = 0; p < 8; p++)
#pragma unroll
        for (int j = 0; j < 8; j++) acc[p][j] = 0ull;

    // ---- async fill of chunk (k0) into buffer buf ----
    auto fill = [&](int buf, int k0) {
        const uint32_t xb = xs_a + (uint32_t)buf * (TCTA * KC * 4);
        const uint32_t wb = ws_a + (uint32_t)buf * (NE * KC * 4);
#pragma unroll
        for (int rr = 0; rr < 16; rr++) {
            const int r = fr + 4 * rr;                 // token-local / expert
            const uint32_t dx = xb + (uint32_t)(r * KC + ((fg ^ ((r >> 4) & 3)) << 2)) * 4;
            cp16(dx, x + (size_t)(t0 + r) * DM + k0 + fg * 4);
            const uint32_t dw = wb + (uint32_t)(r * KC + ((fg ^ (r & 7)) << 2)) * 4;
            cp16(dw, W + (size_t)r * DM + k0 + fg * 4);
        }
        asm volatile("cp.async.commit_group;");
    };

    // prologue: start chunk 0
    fill(0, 0);

    const int xswz = tyq << 2;
    const int wswz = tx << 2;

    for (int c = 0; c < NCHUNK; c++) {
        const int buf = c & 1;

        if (c + 1 < NCHUNK) {
            fill(buf ^ 1, (c + 1) * KC);               // overlap with compute
            asm volatile("cp.async.wait_group 1;");    // chunk c landed
        } else {
            asm volatile("cp.async.wait_group 0;");
        }
        __syncwarp();

        const float* xb = &xsm[buf][tbase * KC];
        const float* wb = &wsm[buf][0];

        // per k: 16 scalar LDS (x) + 8 scalar LDS (w) = 24 wf,
        //        64 FFMA2 = 128 SMSP-cycles -> 4L/F = 0.75
#pragma unroll 8
        for (int kk = 0; kk < KC; kk++) {
            const int kx = kk ^ xswz;
            const int kw = kk ^ wswz;
            ull wd[8];
#pragma unroll
            for (int j = 0; j < 8; j++)
                wd[j] = dup2(wb[(tx + 8 * j) * KC + kw]);
            ull xp[8];
#pragma unroll
            for (int p = 0; p < 8; p++)
                xp[p] = pack2(xb[(2 * p) * KC + kx],
                              xb[(2 * p + 1) * KC + kx]);
#pragma unroll
            for (int p = 0; p < 8; p++)
#pragma unroll
                for (int j = 0; j < 8; j++)
                    acc[p][j] = fma2(xp[p], wd[j], acc[p][j]);
        }
    }

    // ---- epilogue: softmax/argmax per token over the 8 tx-lanes ----
#pragma unroll
    for (int p = 0; p < 8; p++) {
        float la[2][8];
#pragma unroll
        for (int j = 0; j < 8; j++) {
            float2 f = unpack2(acc[p][j]);
            la[0][j] = f.x;
            la[1][j] = f.y;
        }
#pragma unroll
        for (int a = 0; a < 2; a++) {
            const int t = t0 + tbase + 2 * p + a;

            // local argmax; expert ids tx+8j strictly increase with j ->
            // strict '>' keeps the FIRST max (matches jnp.argmax)
            float m = la[a][0];
            int   e = tx;
#pragma unroll
            for (int j = 1; j < 8; j++) {
                const int ej = tx + 8 * j;
                if (la[a][j] > m) { m = la[a][j]; e = ej; }
            }
            // butterfly over the 8-lane tx group (lane = tx + 8*tyq)
#pragma unroll
            for (int msk = 1; msk < 8; msk <<= 1) {
                float om = __shfl_xor_sync(0xffffffffu, m, msk);
                int   oe = __shfl_xor_sync(0xffffffffu, e, msk);
                if (om > m || (om == m && oe < e)) { m = om; e = oe; }
            }

            float s = 0.f;
#pragma unroll
            for (int j = 0; j < 8; j++) s += __expf(la[a][j] - m);
#pragma unroll
            for (int msk = 1; msk < 8; msk <<= 1)
                s += __shfl_xor_sync(0xffffffffu, s, msk);

            float* lg = out + LG_OFF + (size_t)t * NE;
            float* oh = out + (size_t)t * NE;
#pragma unroll
            for (int j = 0; j < 8; j++) {
                const int ej = tx + 8 * j;
                lg[ej] = la[a][j];
                oh[ej] = (ej == e) ? 1.f : 0.f;
            }
            if (tx == 0) out[TP_OFF + t] = 1.0f / s;
        }
    }
}

extern "C" void kernel_launch(void* const* d_in, const int* in_sizes, int n_in,
                              void* d_out, int out_size) {
    const float* x = (const float*)d_in[0];   // [65536, 2048] f32
    const float* W = (const float*)d_in[1];   // [64, 2048] f32
    float* out = (float*)d_out;

    dim3 grid(T_TOKENS / TCTA);   // 1024 one-warp CTAs
    dim3 block(32);
    router_kernel<<<grid, block>>>(x, W, out);
}

// round 16
// speedup vs baseline: 1.0017x; 1.0016x over previous
#include <cuda_runtime.h>
#include <cstdint>
#include <cstddef>

// Problem constants
#define T_TOKENS 65536
#define DM 2048
#define NE 64

// Tiling: 1-warp CTAs, 64 tokens/CTA, per-thread 16 tokens x 8 experts.
// KC=32 chunks, cp.async double-buffered global->smem pipeline (no prefetch
// registers -> no spills, unlike R7's 255-reg version).
#define KC 32
#define NCHUNK (DM / KC)     // 64
#define TCTA 64

// Output layout (flattened tuple, all float32) — validated R4+:
#define TP_OFF ((size_t)T_TOKENS * NE)
#define LG_OFF ((size_t)T_TOKENS * NE + T_TOKENS)

typedef unsigned long long ull;

__device__ __forceinline__ ull fma2(ull a, ull b, ull c) {
    ull d;
    asm("fma.rn.f32x2 %0, %1, %2, %3;" : "=l"(d) : "l"(a), "l"(b), "l"(c));
    return d;
}
__device__ __forceinline__ ull dup2(float w) {
    ull d;
    asm("mov.b64 %0, {%1, %1};" : "=l"(d) : "f"(w));
    return d;
}
__device__ __forceinline__ ull pack2(float lo, float hi) {
    ull d;
    asm("mov.b64 %0, {%1, %2};" : "=l"(d) : "f"(lo), "f"(hi));
    return d;
}
__device__ __forceinline__ float2 unpack2(ull u) {
    float2 f;
    asm("mov.b64 {%0, %1}, %2;" : "=f"(f.x), "=f"(f.y) : "l"(u));
    return f;
}
__device__ __forceinline__ void cp16(uint32_t dst, const void* src) {
    asm volatile("cp.async.cg.shared.global [%0], [%1], 16;"
                 :: "r"(dst), "l"(src));
}

__global__ void __launch_bounds__(32)
router_kernel(const float* __restrict__ x,
              const float* __restrict__ W,
              float* __restrict__ out) {
    // Rows are exactly 32 floats (128B). 16B-granule XOR swizzle gives
    // conflict-free compute loads AND direct cp.async fills:
    //   x granule (t,g)  stored at col 4*(g ^ ((t>>4)&3))
    //   W granule (e,g)  stored at col 4*(g ^ (e&7))
    __shared__ __align__(16) float xsm[2][TCTA * KC];   // 2 x 8 KB
    __shared__ __align__(16) float wsm[2][NE * KC];     // 2 x 8 KB

    const int lane = threadIdx.x;
    const int tx   = lane & 7;        // expert lane: e = tx + 8j
    const int tyq  = lane >> 3;       // token group: tokens tyq*16 .. +15
    const int t0   = blockIdx.x * TCTA;
    const int tbase = tyq * 16;

    // fill mapping: 4 rows x 8 granules per pass, 16 passes
    const int fr = lane >> 3;         // row sub-index 0..3
    const int fg = lane & 7;          // 16B granule 0..7

    const uint32_t xs_a = (uint32_t)__cvta_generic_to_shared(&xsm[0][0]);
    const uint32_t ws_a = (uint32_t)__cvta_generic_to_shared(&wsm[0][0]);

    // acc[p][j]: token pair (tbase+2p, tbase+2p+1) x expert (tx+8j)
    ull acc[8][8];
#pragma unroll
    for (int p = 0; p < 8; p++)
#pragma unroll
        for (int j = 0; j < 8; j++) acc[p][j] = 0ull;

    // ---- async fill of chunk (k0) into buffer buf ----
    auto fill = [&](int buf, int k0) {
        const uint32_t xb = xs_a + (uint32_t)buf * (TCTA * KC * 4);
        const uint32_t wb = ws_a + (uint32_t)buf * (NE * KC * 4);
#pragma unroll
        for (int rr = 0; rr < 16; rr++) {
            const int r = fr + 4 * rr;                 // token-local / expert
            const uint32_t dx = xb + (uint32_t)(r * KC + ((fg ^ ((r >> 4) & 3)) << 2)) * 4;
            cp16(dx, x + (size_t)(t0 + r) * DM + k0 + fg * 4);
            const uint32_t dw = wb + (uint32_t)(r * KC + ((fg ^ (r & 7)) << 2)) * 4;
            cp16(dw, W + (size_t)r * DM + k0 + fg * 4);
        }
        asm volatile("cp.async.commit_group;");
    };

    // prologue: start chunk 0
    fill(0, 0);

    const int xswz = tyq << 2;
    const int wswz = tx << 2;

    for (int c = 0; c < NCHUNK; c++) {
        const int buf = c & 1;

        if (c + 1 < NCHUNK) {
            fill(buf ^ 1, (c + 1) * KC);               // overlap with compute
            asm volatile("cp.async.wait_group 1;");    // chunk c landed
        } else {
            asm volatile("cp.async.wait_group 0;");
        }
        __syncwarp();

        const float* xb = &xsm[buf][tbase * KC];
        const float* wb = &wsm[buf][0];

        // per k: 16 scalar LDS (x) + 8 scalar LDS (w) = 24 wf,
        //        64 FFMA2 = 128 SMSP-cycles -> 4L/F = 0.75
#pragma unroll 8
        for (int kk = 0; kk < KC; kk++) {
            const int kx = kk ^ xswz;
            const int kw = kk ^ wswz;
            ull wd[8];
#pragma unroll
            for (int j = 0; j < 8; j++)
                wd[j] = dup2(wb[(tx + 8 * j) * KC + kw]);
            ull xp[8];
#pragma unroll
            for (int p = 0; p < 8; p++)
                xp[p] = pack2(xb[(2 * p) * KC + kx],
                              xb[(2 * p + 1) * KC + kx]);
#pragma unroll
            for (int p = 0; p < 8; p++)
#pragma unroll
                for (int j = 0; j < 8; j++)
                    acc[p][j] = fma2(xp[p], wd[j], acc[p][j]);
        }
    }

    // ---- epilogue: softmax/argmax per token over the 8 tx-lanes ----
#pragma unroll
    for (int p = 0; p < 8; p++) {
        float la[2][8];
#pragma unroll
        for (int j = 0; j < 8; j++) {
            float2 f = unpack2(acc[p][j]);
            la[0][j] = f.x;
            la[1][j] = f.y;
        }
#pragma unroll
        for (int a = 0; a < 2; a++) {
            const int t = t0 + tbase + 2 * p + a;

            // local argmax; expert ids tx+8j strictly increase with j ->
            // strict '>' keeps the FIRST max (matches jnp.argmax)
            float m = la[a][0];
            int   e = tx;
#pragma unroll
            for (int j = 1; j < 8; j++) {
                const int ej = tx + 8 * j;
                if (la[a][j] > m) { m = la[a][j]; e = ej; }
            }
            // butterfly over the 8-lane tx group (lane = tx + 8*tyq)
#pragma unroll
            for (int msk = 1; msk < 8; msk <<= 1) {
                float om = __shfl_xor_sync(0xffffffffu, m, msk);
                int   oe = __shfl_xor_sync(0xffffffffu, e, msk);
                if (om > m || (om == m && oe < e)) { m = om; e = oe; }
            }

            float s = 0.f;
#pragma unroll
            for (int j = 0; j < 8; j++) s += __expf(la[a][j] - m);
#pragma unroll
            for (int msk = 1; msk < 8; msk <<= 1)
                s += __shfl_xor_sync(0xffffffffu, s, msk);

            float* lg = out + LG_OFF + (size_t)t * NE;
            float* oh = out + (size_t)t * NE;
#pragma unroll
            for (int j = 0; j < 8; j++) {
                const int ej = tx + 8 * j;
                lg[ej] = la[a][j];
                oh[ej] = (ej == e) ? 1.f : 0.f;
            }
            if (tx == 0) out[TP_OFF + t] = 1.0f / s;
        }
    }
}

extern "C" void kernel_launch(void* const* d_in, const int* in_sizes, int n_in,
                              void* d_out, int out_size) {
    const float* x = (const float*)d_in[0];   // [65536, 2048] f32
    const float* W = (const float*)d_in[1];   // [64, 2048] f32
    float* out = (float*)d_out;

    dim3 grid(T_TOKENS / TCTA);   // 1024 one-warp CTAs
    dim3 block(32);
    router_kernel<<<grid, block>>>(x, W, out);
}